// round 1
// baseline (speedup 1.0000x reference)
#include <cuda_runtime.h>

#define BATCH        16384
#define NUM_FIELDS   20
#define NUM_FEATURES 100000
#define LATENT_DIM   64

// One warp per batch sample.
// - lanes 0..19 load the 20 feature indices for this sample (one LDG.32 each)
// - each lane owns dims [2*lane, 2*lane+1] -> one float2 per embedding row
// - 20 fully-unrolled independent row loads per lane => MLP=20, coalesced 256B/row
// - combined warp reduction of (sum v)^2 - sum v^2 and the integer linear term
__global__ __launch_bounds__(256)
void ffm_kernel(const int* __restrict__ x,
                const float* __restrict__ emb,
                float* __restrict__ out)
{
    const int gwarp = (blockIdx.x * blockDim.x + threadIdx.x) >> 5;
    const int lane  = threadIdx.x & 31;
    if (gwarp >= BATCH) return;

    // Load this sample's 20 indices (lanes >= 20 hold 0 so the linear-term
    // reduction is unaffected).
    int xi = 0;
    if (lane < NUM_FIELDS) xi = __ldg(x + gwarp * NUM_FIELDS + lane);

    float2 s  = make_float2(0.f, 0.f);   // per-lane partial of sum_f V[f]
    float  sq = 0.f;                     // per-lane partial of sum_f V[f]^2

    #pragma unroll
    for (int f = 0; f < NUM_FIELDS; ++f) {
        const int idx = __shfl_sync(0xffffffffu, xi, f);
        const float2* row = reinterpret_cast<const float2*>(
            emb + ((size_t)f * NUM_FEATURES + (size_t)idx) * LATENT_DIM);
        const float2 v = __ldg(row + lane);
        s.x += v.x;
        s.y += v.y;
        sq  = fmaf(v.x, v.x, sq);
        sq  = fmaf(v.y, v.y, sq);
    }

    // part = sum_d s_d^2 - sum_{f,d} v^2  (per-lane partial, then warp-reduce)
    float part = fmaf(s.x, s.x, s.y * s.y) - sq;
    int   lin  = xi;

    #pragma unroll
    for (int o = 16; o > 0; o >>= 1) {
        part += __shfl_xor_sync(0xffffffffu, part, o);
        lin  += __shfl_xor_sync(0xffffffffu, lin,  o);
    }

    if (lane == 0)
        out[gwarp] = (float)lin + 0.5f * part;
}

extern "C" void kernel_launch(void* const* d_in, const int* in_sizes, int n_in,
                              void* d_out, int out_size)
{
    const int*   x   = (const int*)d_in[0];     // (16384, 20) int32
    // d_in[1] = field_indices (arange(20)) — unused, it's the identity
    const float* emb = (const float*)d_in[2];   // (20, 100000, 64) fp32
    float*       out = (float*)d_out;           // (16384,) fp32

    const int threads = 256;                    // 8 warps = 8 samples / block
    const int blocks  = (BATCH * 32 + threads - 1) / threads;  // 2048
    ffm_kernel<<<blocks, threads>>>(x, emb, out);
}

// round 2
// speedup vs baseline: 1.2135x; 1.2135x over previous
#include <cuda_runtime.h>

#define BATCH        16384
#define NUM_FIELDS   20
#define NUM_FEATURES 100000
#define LATENT_DIM   64

// Two batch samples per warp, one per half-warp (16 lanes each).
// Each lane owns 4 of the 64 dims -> one LDG.128 (float4) per embedding row.
// 20 fully-unrolled independent LDG.128 per lane => 10 KiB in flight per warp.
// Per half-warp, each row read is 16 lanes x 16 B = 256 B fully coalesced.
__global__ __launch_bounds__(256)
void ffm_kernel(const int* __restrict__ x,
                const float* __restrict__ emb,
                float* __restrict__ out)
{
    const int gwarp = (blockIdx.x * blockDim.x + threadIdx.x) >> 5;
    const int lane  = threadIdx.x & 31;
    const int half  = lane >> 4;          // which sample within the warp
    const int lh    = lane & 15;          // lane within half-warp
    const int s     = gwarp * 2 + half;   // batch sample id
    if (s >= BATCH) return;

    // 20 indices per half-warp: lanes 0..15 of the half hold fields 0..15,
    // lanes 0..3 additionally hold fields 16..19.
    const int* xrow = x + s * NUM_FIELDS;
    int xi0 = __ldg(xrow + lh);                       // fields 0..15
    int xi1 = (lh < NUM_FIELDS - 16) ? __ldg(xrow + 16 + lh) : 0;  // 16..19

    float4 sv = make_float4(0.f, 0.f, 0.f, 0.f);      // partial of sum_f V[f]
    float  sq = 0.f;                                  // partial of sum V^2

    #pragma unroll
    for (int f = 0; f < NUM_FIELDS; ++f) {
        int idx;
        if (f < 16) idx = __shfl_sync(0xffffffffu, xi0, f, 16);
        else        idx = __shfl_sync(0xffffffffu, xi1, f - 16, 16);
        const float4* row = reinterpret_cast<const float4*>(
            emb + ((size_t)f * NUM_FEATURES + (size_t)idx) * LATENT_DIM);
        const float4 v = __ldg(row + lh);
        sv.x += v.x;  sv.y += v.y;  sv.z += v.z;  sv.w += v.w;
        sq = fmaf(v.x, v.x, sq);
        sq = fmaf(v.y, v.y, sq);
        sq = fmaf(v.z, v.z, sq);
        sq = fmaf(v.w, v.w, sq);
    }

    float part = fmaf(sv.x, sv.x, fmaf(sv.y, sv.y,
                 fmaf(sv.z, sv.z, sv.w * sv.w))) - sq;
    int   lin  = xi0 + xi1;

    // Reduce within the 16-lane half-warp.
    #pragma unroll
    for (int o = 8; o > 0; o >>= 1) {
        part += __shfl_xor_sync(0xffffffffu, part, o);
        lin  += __shfl_xor_sync(0xffffffffu, lin,  o);
    }

    if (lh == 0)
        out[s] = (float)lin + 0.5f * part;
}

extern "C" void kernel_launch(void* const* d_in, const int* in_sizes, int n_in,
                              void* d_out, int out_size)
{
    const int*   x   = (const int*)d_in[0];     // (16384, 20) int32
    // d_in[1] = field_indices (arange(20)) — identity, unused
    const float* emb = (const float*)d_in[2];   // (20, 100000, 64) fp32
    float*       out = (float*)d_out;           // (16384,) fp32

    const int threads = 256;                    // 8 warps = 16 samples / block
    const int warps   = (BATCH + 1) / 2;        // 8192 warps
    const int blocks  = (warps * 32 + threads - 1) / threads;  // 1024
    ffm_kernel<<<blocks, threads>>>(x, emb, out);
}